// round 1
// baseline (speedup 1.0000x reference)
#include <cuda_runtime.h>

// Problem constants
#define T_   4
#define B_   2
#define C_   384
#define L_   1024
#define H_   8
#define D_   48
#define C2_  768
#define BH_  16            // B_*H_
#define BCL  (B_*C_*L_)    // 786432
#define LL   (L_*L_)       // 1048576

// Scratch (device globals: no allocation allowed in kernel_launch)
__device__ float         g_xs [T_*BCL];          // spikes of x  (12.6 MB)
__device__ float         g_y  [T_*B_*C2_*L_];    // bn1(W_w @ xs) (25 MB)
__device__ unsigned char g_spk[T_*BH_*LL];       // attn spikes  (67 MB)
__device__ float         g_o1 [T_*BCL];          // y2 @ spk, then its spikes (in-place)

__device__ __forceinline__ void fma4x4(float acc[4][4], float4 a, float4 b) {
    acc[0][0] += a.x*b.x; acc[0][1] += a.x*b.y; acc[0][2] += a.x*b.z; acc[0][3] += a.x*b.w;
    acc[1][0] += a.y*b.x; acc[1][1] += a.y*b.y; acc[1][2] += a.y*b.z; acc[1][3] += a.y*b.w;
    acc[2][0] += a.z*b.x; acc[2][1] += a.z*b.y; acc[2][2] += a.z*b.z; acc[2][3] += a.z*b.w;
    acc[3][0] += a.w*b.x; acc[3][1] += a.w*b.y; acc[3][2] += a.w*b.z; acc[3][3] += a.w*b.w;
}

// ---------------------------------------------------------------------------
// K1: membrane scan over x -> binary spikes xs (float 0/1)
// ---------------------------------------------------------------------------
__global__ __launch_bounds__(256) void k_scan_x(const float* __restrict__ x) {
    int i = blockIdx.x * 256 + threadIdx.x;
    if (i >= BCL) return;
    float mem = 0.f, sp = 0.f;
#pragma unroll
    for (int t = 0; t < T_; ++t) {
        mem = mem * 0.25f * (1.f - sp) + x[(size_t)t * BCL + i];
        sp  = (mem > 0.5f) ? 1.f : 0.f;
        g_xs[(size_t)t * BCL + i] = sp;
    }
}

// ---------------------------------------------------------------------------
// K2 / K6: batched GEMM  Y[tb] = bn(W @ X[tb]) (+ residual)
//   W: [M x 384] row-major. X: [384 x 1024] per batch. 8 batches (t,b).
//   which==0: X=g_xs, Y=g_y (bn1).  which==1: X=g_o1, Y=outExt (bn2 + x).
// ---------------------------------------------------------------------------
__global__ __launch_bounds__(256) void k_gemm_bn(
    const float* __restrict__ W,
    const float* __restrict__ gamma, const float* __restrict__ beta,
    const float* __restrict__ mean,  const float* __restrict__ var,
    const float* __restrict__ resid,           // nullptr or x
    float* __restrict__ outExt, int M, int which)
{
    const float* Xb = (which == 0) ? g_xs : g_o1;
    float*       Yb = (which == 0) ? g_y  : outExt;

    const int tid = threadIdx.x;
    const int tx = tid & 15, ty = tid >> 4;
    const int n0 = blockIdx.x * 64;
    const int m0 = blockIdx.y * 64;
    const int tb = blockIdx.z;

    const float* X = Xb + (size_t)tb * (C_ * L_);
    float*       Y = Yb + (size_t)tb * (size_t)M * L_;

    __shared__ float As[16][64];
    __shared__ float Bs[16][64];

    float acc[4][4] = {};

    const int ar = tid >> 2;          // A tile row (m), 0..63
    const int ac = (tid & 3) * 4;     // A tile k-quad
    const int br = tid >> 4;          // B tile row (k), 0..15
    const int bc = (tid & 15) * 4;    // B tile n-quad

    for (int kt = 0; kt < C_; kt += 16) {
        float4 av = *(const float4*)(W + (size_t)(m0 + ar) * C_ + kt + ac);
        float4 bv = *(const float4*)(X + (size_t)(kt + br) * L_ + n0 + bc);
        As[ac+0][ar] = av.x; As[ac+1][ar] = av.y; As[ac+2][ar] = av.z; As[ac+3][ar] = av.w;
        *(float4*)&Bs[br][bc] = bv;
        __syncthreads();
#pragma unroll
        for (int k = 0; k < 16; ++k) {
            float4 a = *(const float4*)&As[k][ty * 4];
            float4 b = *(const float4*)&Bs[k][tx * 4];
            fma4x4(acc, a, b);
        }
        __syncthreads();
    }

#pragma unroll
    for (int i = 0; i < 4; ++i) {
        int m = m0 + ty * 4 + i;
        float inv = gamma[m] / sqrtf(var[m] + 1e-5f);
        float off = beta[m] - mean[m] * inv;
        float4 r;
        r.x = acc[i][0] * inv + off;
        r.y = acc[i][1] * inv + off;
        r.z = acc[i][2] * inv + off;
        r.w = acc[i][3] * inv + off;
        if (resid) {
            const float4 rx = *(const float4*)(resid + (size_t)tb * (C_ * L_) +
                                               (size_t)m * L_ + n0 + tx * 4);
            r.x += rx.x; r.y += rx.y; r.z += rx.z; r.w += rx.w;
        }
        *(float4*)(Y + (size_t)m * L_ + n0 + tx * 4) = r;
    }
}

// ---------------------------------------------------------------------------
// K3: fused attn GEMM (K=48) + membrane scan over t -> uint8 spikes.
//   attn_t[l,m] = sum_d y1_t[d,l] * xr_t[d,m]; scan over t=0..3 in registers.
//   grid (m_tiles=16, l_tiles=16, bh=16)
// ---------------------------------------------------------------------------
__global__ __launch_bounds__(256) void k_attn_fused() {
    const int bh = blockIdx.z;
    const int b = bh >> 3, h = bh & 7;
    const int l0 = blockIdx.y * 64;
    const int m0 = blockIdx.x * 64;

    __shared__ float As[48][64];   // y1[d][l-tile]
    __shared__ float Bs[48][64];   // xr[d][m-tile]

    const int tid = threadIdx.x;
    const int tx = tid & 15, ty = tid >> 4;

    float mem[4][4];
#pragma unroll
    for (int i = 0; i < 4; ++i)
#pragma unroll
        for (int j = 0; j < 4; ++j) mem[i][j] = 0.f;

    for (int t = 0; t < T_; ++t) {
        const float* y1 = g_y  + ((size_t)(t * B_ + b) * C2_ + h * 96) * L_;
        const float* xr = g_xs + ((size_t)(t * B_ + b) * C_  + h * D_) * L_;
#pragma unroll
        for (int q = 0; q < 3; ++q) {
            int idx = tid + q * 256;       // 0..767
            int row = idx >> 4;            // d
            int c4  = (idx & 15) << 2;
            *(float4*)&As[row][c4] = *(const float4*)(y1 + (size_t)row * L_ + l0 + c4);
            *(float4*)&Bs[row][c4] = *(const float4*)(xr + (size_t)row * L_ + m0 + c4);
        }
        __syncthreads();

        float acc[4][4] = {};
#pragma unroll 8
        for (int k = 0; k < 48; ++k) {
            float4 a = *(const float4*)&As[k][ty * 4];
            float4 b2 = *(const float4*)&Bs[k][tx * 4];
            fma4x4(acc, a, b2);
        }

        unsigned char* o = g_spk + (size_t)(t * BH_ + bh) * LL;
#pragma unroll
        for (int i = 0; i < 4; ++i) {
            uchar4 s;
            float* mi = mem[i];
#pragma unroll
            for (int j = 0; j < 4; ++j)
                mi[j] = mi[j] * 0.25f * ((mi[j] > 0.5f) ? 0.f : 1.f) + acc[i][j];
            s.x = (mi[0] > 0.5f) ? 1 : 0;
            s.y = (mi[1] > 0.5f) ? 1 : 0;
            s.z = (mi[2] > 0.5f) ? 1 : 0;
            s.w = (mi[3] > 0.5f) ? 1 : 0;
            *(uchar4*)(o + (size_t)(l0 + ty * 4 + i) * L_ + m0 + tx * 4) = s;
        }
        __syncthreads();
    }
}

// ---------------------------------------------------------------------------
// K4: out1[d,m] = sum_l y2[d,l] * spk[l,m]   (M=48, N=1024 tiled 128, K=1024)
//   grid (8, 1, 64)
// ---------------------------------------------------------------------------
__global__ __launch_bounds__(256) void k_gemm2() {
    const int z = blockIdx.z;              // t*16 + bh
    const int t = z >> 4, bh = z & 15;
    const int b = bh >> 3, h = bh & 7;

    const float*         y2  = g_y   + ((size_t)(t * B_ + b) * C2_ + h * 96 + 48) * L_;
    const unsigned char* S   = g_spk + (size_t)z * LL;
    float*               out = g_o1  + ((size_t)(t * B_ + b) * C_ + h * D_) * L_;

    const int m0 = blockIdx.x * 128;
    const int tid = threadIdx.x;
    const int tx = tid & 15, ty = tid >> 4;

    __shared__ float As[32][48];    // y2 [k][d]
    __shared__ float Bs[32][128];   // spikes as float [k][m]

    float acc[3][8] = {};

    for (int kt = 0; kt < L_; kt += 32) {
#pragma unroll
        for (int q = 0; q < 6; ++q) {
            int idx = tid + q * 256;       // 0..1535
            int dd = idx >> 5;
            int kk = idx & 31;
            As[kk][dd] = y2[(size_t)dd * L_ + kt + kk];
        }
#pragma unroll
        for (int q = 0; q < 4; ++q) {
            int idx = tid + q * 256;       // 0..1023
            int kk = idx >> 5;
            int c4 = (idx & 31) * 4;
            uchar4 v = *(const uchar4*)(S + (size_t)(kt + kk) * L_ + m0 + c4);
            Bs[kk][c4 + 0] = (float)v.x;
            Bs[kk][c4 + 1] = (float)v.y;
            Bs[kk][c4 + 2] = (float)v.z;
            Bs[kk][c4 + 3] = (float)v.w;
        }
        __syncthreads();
#pragma unroll 16
        for (int k = 0; k < 32; ++k) {
            float a0 = As[k][ty * 3 + 0];
            float a1 = As[k][ty * 3 + 1];
            float a2 = As[k][ty * 3 + 2];
            float4 b0 = *(const float4*)&Bs[k][tx * 8];
            float4 b1 = *(const float4*)&Bs[k][tx * 8 + 4];
            acc[0][0]+=a0*b0.x; acc[0][1]+=a0*b0.y; acc[0][2]+=a0*b0.z; acc[0][3]+=a0*b0.w;
            acc[0][4]+=a0*b1.x; acc[0][5]+=a0*b1.y; acc[0][6]+=a0*b1.z; acc[0][7]+=a0*b1.w;
            acc[1][0]+=a1*b0.x; acc[1][1]+=a1*b0.y; acc[1][2]+=a1*b0.z; acc[1][3]+=a1*b0.w;
            acc[1][4]+=a1*b1.x; acc[1][5]+=a1*b1.y; acc[1][6]+=a1*b1.z; acc[1][7]+=a1*b1.w;
            acc[2][0]+=a2*b0.x; acc[2][1]+=a2*b0.y; acc[2][2]+=a2*b0.z; acc[2][3]+=a2*b0.w;
            acc[2][4]+=a2*b1.x; acc[2][5]+=a2*b1.y; acc[2][6]+=a2*b1.z; acc[2][7]+=a2*b1.w;
        }
        __syncthreads();
    }

#pragma unroll
    for (int i = 0; i < 3; ++i) {
        int dd = ty * 3 + i;
        float4 r0 = make_float4(acc[i][0], acc[i][1], acc[i][2], acc[i][3]);
        float4 r1 = make_float4(acc[i][4], acc[i][5], acc[i][6], acc[i][7]);
        *(float4*)(out + (size_t)dd * L_ + m0 + tx * 8)     = r0;
        *(float4*)(out + (size_t)dd * L_ + m0 + tx * 8 + 4) = r1;
    }
}

// ---------------------------------------------------------------------------
// K5: membrane scan over out1 (in-place -> binary spikes)
// ---------------------------------------------------------------------------
__global__ __launch_bounds__(256) void k_scan_o1() {
    int i = blockIdx.x * 256 + threadIdx.x;
    if (i >= BCL) return;
    float mem = 0.f, sp = 0.f;
#pragma unroll
    for (int t = 0; t < T_; ++t) {
        mem = mem * 0.25f * (1.f - sp) + g_o1[(size_t)t * BCL + i];
        sp  = (mem > 0.5f) ? 1.f : 0.f;
        g_o1[(size_t)t * BCL + i] = sp;
    }
}

// ---------------------------------------------------------------------------
extern "C" void kernel_launch(void* const* d_in, const int* in_sizes, int n_in,
                              void* d_out, int out_size) {
    (void)in_sizes; (void)n_in; (void)out_size;
    const float* x   = (const float*)d_in[0];
    const float* W_w = (const float*)d_in[1];
    const float* g1  = (const float*)d_in[2];
    const float* be1 = (const float*)d_in[3];
    const float* me1 = (const float*)d_in[4];
    const float* v1  = (const float*)d_in[5];
    const float* pw  = (const float*)d_in[6];
    const float* g2  = (const float*)d_in[7];
    const float* be2 = (const float*)d_in[8];
    const float* me2 = (const float*)d_in[9];
    const float* v2  = (const float*)d_in[10];
    float* out = (float*)d_out;

    k_scan_x<<<BCL / 256, 256>>>(x);
    k_gemm_bn<<<dim3(L_ / 64, C2_ / 64, T_ * B_), 256>>>(
        W_w, g1, be1, me1, v1, nullptr, nullptr, C2_, 0);
    k_attn_fused<<<dim3(L_ / 64, L_ / 64, BH_), 256>>>();
    k_gemm2<<<dim3(L_ / 128, 1, T_ * BH_), 256>>>();
    k_scan_o1<<<BCL / 256, 256>>>();
    k_gemm_bn<<<dim3(L_ / 64, C_ / 64, T_ * B_), 256>>>(
        pw, g2, be2, me2, v2, x, out, C_, 1);
}

// round 2
// speedup vs baseline: 1.5468x; 1.5468x over previous
#include <cuda_runtime.h>

// Problem constants
#define T_   4
#define B_   2
#define C_   384
#define L_   1024
#define H_   8
#define D_   48
#define C2_  768
#define BH_  16            // B_*H_
#define BCL  (B_*C_*L_)    // 786432
#define LL   (L_*L_)       // 1048576

// Scratch (device globals)
__device__ float         g_xs [T_*BCL];          // spikes of x (float 0/1)
__device__ float         g_y  [T_*B_*C2_*L_];    // bn1(W_w @ xs)
__device__ unsigned char g_spk[T_*BH_*LL];       // attn spikes (uint8)
__device__ float         g_o1 [T_*BCL];          // y2 @ spk, then spikes in place

typedef unsigned long long u64;

// ---- packed f32x2 helpers (2x fp32 FMA throughput on sm_103a) ----
__device__ __forceinline__ u64 pk2(float lo, float hi) {
    u64 r; asm("mov.b64 %0,{%1,%2};" : "=l"(r) : "f"(lo), "f"(hi)); return r;
}
__device__ __forceinline__ void upk2(float& lo, float& hi, u64 v) {
    asm("mov.b64 {%0,%1},%2;" : "=f"(lo), "=f"(hi) : "l"(v));
}
__device__ __forceinline__ void ffma2(u64& d, u64 a, u64 b) {
    asm("fma.rn.f32x2 %0,%1,%2,%0;" : "+l"(d) : "l"(a), "l"(b));
}

// ---------------------------------------------------------------------------
// K1: membrane scan over x -> binary spikes xs (float 0/1)
// ---------------------------------------------------------------------------
__global__ __launch_bounds__(256) void k_scan_x(const float* __restrict__ x) {
    int i = blockIdx.x * 256 + threadIdx.x;
    if (i >= BCL) return;
    float mem = 0.f, sp = 0.f;
#pragma unroll
    for (int t = 0; t < T_; ++t) {
        mem = mem * 0.25f * (1.f - sp) + x[(size_t)t * BCL + i];
        sp  = (mem > 0.5f) ? 1.f : 0.f;
        g_xs[(size_t)t * BCL + i] = sp;
    }
}

// ---------------------------------------------------------------------------
// K2 / K6: batched GEMM Y[tb] = bn(W @ X[tb]) (+ residual)
//   Block tile 64M x 128N, thread tile 8M x 4N (2 f32x2 accs per row).
//   Warp w owns rows m0+w*8.. (A loads are warp-broadcast); lane owns n=lane*4.
// ---------------------------------------------------------------------------
__global__ __launch_bounds__(256) void k_gemm_bn(
    const float* __restrict__ W,
    const float* __restrict__ gamma, const float* __restrict__ beta,
    const float* __restrict__ mean,  const float* __restrict__ var,
    const float* __restrict__ resid,
    float* __restrict__ outExt, int M, int which)
{
    const float* Xb = (which == 0) ? g_xs : g_o1;
    float*       Yb = (which == 0) ? g_y  : outExt;

    const int tid  = threadIdx.x;
    const int lane = tid & 31, w = tid >> 5;
    const int n0 = blockIdx.x * 128;
    const int m0 = blockIdx.y * 64;
    const int tb = blockIdx.z;

    const float* X = Xb + (size_t)tb * (C_ * L_);
    float*       Y = Yb + (size_t)tb * (size_t)M * L_;

    __shared__ float As[16][68];   // padded: kills STS bank conflicts, keeps 16B align
    __shared__ float Bs[16][128];

    u64 acc[8][2];
#pragma unroll
    for (int i = 0; i < 8; ++i) { acc[i][0] = 0ull; acc[i][1] = 0ull; }

    const int am = tid >> 2, ak = (tid & 3) * 4;    // A fill: W[m][k..k+3]
    const int bk = tid >> 4, bn = (tid & 15) * 8;   // B fill: 2 float4 per thread

    for (int kt = 0; kt < C_; kt += 16) {
        float4 av = *(const float4*)(W + (size_t)(m0 + am) * C_ + kt + ak);
        As[ak + 0][am] = av.x; As[ak + 1][am] = av.y;
        As[ak + 2][am] = av.z; As[ak + 3][am] = av.w;
        *(float4*)&Bs[bk][bn]     = *(const float4*)(X + (size_t)(kt + bk) * L_ + n0 + bn);
        *(float4*)&Bs[bk][bn + 4] = *(const float4*)(X + (size_t)(kt + bk) * L_ + n0 + bn + 4);
        __syncthreads();
#pragma unroll
        for (int k = 0; k < 16; ++k) {
            float4 bv = *(const float4*)&Bs[k][lane * 4];
            u64 b0 = pk2(bv.x, bv.y), b1 = pk2(bv.z, bv.w);
            float4 a0 = *(const float4*)&As[k][w * 8];
            float4 a1 = *(const float4*)&As[k][w * 8 + 4];
            float a[8] = {a0.x, a0.y, a0.z, a0.w, a1.x, a1.y, a1.z, a1.w};
#pragma unroll
            for (int i = 0; i < 8; ++i) {
                u64 s = pk2(a[i], a[i]);
                ffma2(acc[i][0], s, b0);
                ffma2(acc[i][1], s, b1);
            }
        }
        __syncthreads();
    }

#pragma unroll
    for (int i = 0; i < 8; ++i) {
        int m = m0 + w * 8 + i;
        float inv = gamma[m] / sqrtf(var[m] + 1e-5f);
        float off = beta[m] - mean[m] * inv;
        float r0, r1, r2, r3;
        upk2(r0, r1, acc[i][0]); upk2(r2, r3, acc[i][1]);
        float4 r = make_float4(r0 * inv + off, r1 * inv + off,
                               r2 * inv + off, r3 * inv + off);
        if (resid) {
            const float4 rx = *(const float4*)(resid + (size_t)tb * (C_ * L_) +
                                               (size_t)m * L_ + n0 + lane * 4);
            r.x += rx.x; r.y += rx.y; r.z += rx.z; r.w += rx.w;
        }
        *(float4*)(Y + (size_t)m * L_ + n0 + lane * 4) = r;
    }
}

// ---------------------------------------------------------------------------
// K3: fused attn GEMM (K=48) + membrane scan over t -> uint8 spikes.
//   Block tile 64L x 128M, thread tile 8L x 4M. A (y1) is warp-broadcast.
// ---------------------------------------------------------------------------
__global__ __launch_bounds__(256) void k_attn_fused() {
    const int bh = blockIdx.z;
    const int b = bh >> 3, h = bh & 7;
    const int l0 = blockIdx.y * 64;
    const int m0 = blockIdx.x * 128;

    const int tid = threadIdx.x;
    const int lane = tid & 31, w = tid >> 5;

    __shared__ float As[48][64];    // y1[d][l-tile]
    __shared__ float Bs[48][128];   // xr[d][m-tile]

    float mem[8][4];
#pragma unroll
    for (int i = 0; i < 8; ++i)
#pragma unroll
        for (int j = 0; j < 4; ++j) mem[i][j] = 0.f;

    for (int t = 0; t < T_; ++t) {
        const float* y1 = g_y  + ((size_t)(t * B_ + b) * C2_ + h * 96) * L_;
        const float* xr = g_xs + ((size_t)(t * B_ + b) * C_  + h * D_) * L_;
#pragma unroll
        for (int q = 0; q < 3; ++q) {
            int idx = tid + q * 256;            // 0..767
            int d = idx >> 4, lc = (idx & 15) * 4;
            *(float4*)&As[d][lc] = *(const float4*)(y1 + (size_t)d * L_ + l0 + lc);
        }
#pragma unroll
        for (int q = 0; q < 6; ++q) {
            int idx = tid + q * 256;            // 0..1535
            int d = idx >> 5, mc = (idx & 31) * 4;
            *(float4*)&Bs[d][mc] = *(const float4*)(xr + (size_t)d * L_ + m0 + mc);
        }
        __syncthreads();

        u64 acc[8][2];
#pragma unroll
        for (int i = 0; i < 8; ++i) { acc[i][0] = 0ull; acc[i][1] = 0ull; }

#pragma unroll 4
        for (int k = 0; k < 48; ++k) {
            float4 bv = *(const float4*)&Bs[k][lane * 4];
            u64 b0 = pk2(bv.x, bv.y), b1 = pk2(bv.z, bv.w);
            float4 a0 = *(const float4*)&As[k][w * 8];
            float4 a1 = *(const float4*)&As[k][w * 8 + 4];
            float a[8] = {a0.x, a0.y, a0.z, a0.w, a1.x, a1.y, a1.z, a1.w};
#pragma unroll
            for (int i = 0; i < 8; ++i) {
                u64 s = pk2(a[i], a[i]);
                ffma2(acc[i][0], s, b0);
                ffma2(acc[i][1], s, b1);
            }
        }

        unsigned char* o = g_spk + (size_t)(t * BH_ + bh) * LL;
#pragma unroll
        for (int i = 0; i < 8; ++i) {
            float v0, v1, v2, v3;
            upk2(v0, v1, acc[i][0]); upk2(v2, v3, acc[i][1]);
            float* mi = mem[i];
            mi[0] = mi[0] * 0.25f * ((mi[0] > 0.5f) ? 0.f : 1.f) + v0;
            mi[1] = mi[1] * 0.25f * ((mi[1] > 0.5f) ? 0.f : 1.f) + v1;
            mi[2] = mi[2] * 0.25f * ((mi[2] > 0.5f) ? 0.f : 1.f) + v2;
            mi[3] = mi[3] * 0.25f * ((mi[3] > 0.5f) ? 0.f : 1.f) + v3;
            uchar4 s;
            s.x = (mi[0] > 0.5f) ? 1 : 0;
            s.y = (mi[1] > 0.5f) ? 1 : 0;
            s.z = (mi[2] > 0.5f) ? 1 : 0;
            s.w = (mi[3] > 0.5f) ? 1 : 0;
            *(uchar4*)(o + (size_t)(l0 + w * 8 + i) * L_ + m0 + lane * 4) = s;
        }
        __syncthreads();
    }
}

// ---------------------------------------------------------------------------
// K4: out1[d,m] = sum_l y2[d,l] * spk[l,m]   (M=48, N=1024 tiled 256, K=1024)
//   Block tile 48M x 256N, thread tile 6M x 8N (N split in two 128-halves
//   so both B LDS.128 reads are conflict-free). A (y2) is warp-broadcast.
// ---------------------------------------------------------------------------
__global__ __launch_bounds__(256) void k_gemm2() {
    const int z = blockIdx.z;              // t*16 + bh
    const int t = z >> 4, bh = z & 15;
    const int b = bh >> 3, h = bh & 7;

    const float*         y2  = g_y   + ((size_t)(t * B_ + b) * C2_ + h * 96 + 48) * L_;
    const unsigned char* S   = g_spk + (size_t)z * LL;
    float*               out = g_o1  + ((size_t)(t * B_ + b) * C_ + h * D_) * L_;

    const int n0 = blockIdx.x * 256;
    const int tid = threadIdx.x;
    const int lane = tid & 31, w = tid >> 5;

    __shared__ float As[16][50];    // y2^T [k][d], padded (even, conflict-free)
    __shared__ float Bs[16][256];   // spikes as float [k][n]

    u64 acc[6][4];
#pragma unroll
    for (int i = 0; i < 6; ++i)
#pragma unroll
        for (int j = 0; j < 4; ++j) acc[i][j] = 0ull;

    for (int kt = 0; kt < L_; kt += 16) {
#pragma unroll
        for (int q = 0; q < 3; ++q) {
            int idx = tid + q * 256;           // 0..767
            int d = idx >> 4, k = idx & 15;
            As[k][d] = y2[(size_t)d * L_ + kt + k];
        }
#pragma unroll
        for (int q = 0; q < 4; ++q) {
            int idx = tid + q * 256;           // 0..1023
            int k = idx >> 6, c = (idx & 63) * 4;
            uchar4 v = *(const uchar4*)(S + (size_t)(kt + k) * L_ + n0 + c);
            float4 f;
            f.x = v.x ? 1.f : 0.f; f.y = v.y ? 1.f : 0.f;
            f.z = v.z ? 1.f : 0.f; f.w = v.w ? 1.f : 0.f;
            *(float4*)&Bs[k][c] = f;
        }
        __syncthreads();
#pragma unroll
        for (int k = 0; k < 16; ++k) {
            float4 bv0 = *(const float4*)&Bs[k][lane * 4];
            float4 bv1 = *(const float4*)&Bs[k][128 + lane * 4];
            u64 b0 = pk2(bv0.x, bv0.y), b1 = pk2(bv0.z, bv0.w);
            u64 b2 = pk2(bv1.x, bv1.y), b3 = pk2(bv1.z, bv1.w);
            float2 a01 = *(const float2*)&As[k][w * 6];
            float2 a23 = *(const float2*)&As[k][w * 6 + 2];
            float2 a45 = *(const float2*)&As[k][w * 6 + 4];
            float a[6] = {a01.x, a01.y, a23.x, a23.y, a45.x, a45.y};
#pragma unroll
            for (int i = 0; i < 6; ++i) {
                u64 s = pk2(a[i], a[i]);
                ffma2(acc[i][0], s, b0);
                ffma2(acc[i][1], s, b1);
                ffma2(acc[i][2], s, b2);
                ffma2(acc[i][3], s, b3);
            }
        }
        __syncthreads();
    }

#pragma unroll
    for (int i = 0; i < 6; ++i) {
        int d = w * 6 + i;
        float r0, r1, r2, r3;
        upk2(r0, r1, acc[i][0]); upk2(r2, r3, acc[i][1]);
        *(float4*)(out + (size_t)d * L_ + n0 + lane * 4) = make_float4(r0, r1, r2, r3);
        upk2(r0, r1, acc[i][2]); upk2(r2, r3, acc[i][3]);
        *(float4*)(out + (size_t)d * L_ + n0 + 128 + lane * 4) = make_float4(r0, r1, r2, r3);
    }
}

// ---------------------------------------------------------------------------
// K5: membrane scan over out1 (in-place -> binary spikes)
// ---------------------------------------------------------------------------
__global__ __launch_bounds__(256) void k_scan_o1() {
    int i = blockIdx.x * 256 + threadIdx.x;
    if (i >= BCL) return;
    float mem = 0.f, sp = 0.f;
#pragma unroll
    for (int t = 0; t < T_; ++t) {
        mem = mem * 0.25f * (1.f - sp) + g_o1[(size_t)t * BCL + i];
        sp  = (mem > 0.5f) ? 1.f : 0.f;
        g_o1[(size_t)t * BCL + i] = sp;
    }
}

// ---------------------------------------------------------------------------
extern "C" void kernel_launch(void* const* d_in, const int* in_sizes, int n_in,
                              void* d_out, int out_size) {
    (void)in_sizes; (void)n_in; (void)out_size;
    const float* x   = (const float*)d_in[0];
    const float* W_w = (const float*)d_in[1];
    const float* g1  = (const float*)d_in[2];
    const float* be1 = (const float*)d_in[3];
    const float* me1 = (const float*)d_in[4];
    const float* v1  = (const float*)d_in[5];
    const float* pw  = (const float*)d_in[6];
    const float* g2  = (const float*)d_in[7];
    const float* be2 = (const float*)d_in[8];
    const float* me2 = (const float*)d_in[9];
    const float* v2  = (const float*)d_in[10];
    float* out = (float*)d_out;

    k_scan_x<<<BCL / 256, 256>>>(x);
    k_gemm_bn<<<dim3(L_ / 128, C2_ / 64, T_ * B_), 256>>>(
        W_w, g1, be1, me1, v1, nullptr, nullptr, C2_, 0);
    k_attn_fused<<<dim3(L_ / 128, L_ / 64, BH_), 256>>>();
    k_gemm2<<<dim3(L_ / 256, 1, T_ * BH_), 256>>>();
    k_scan_o1<<<BCL / 256, 256>>>();
    k_gemm_bn<<<dim3(L_ / 128, C_ / 64, T_ * B_), 256>>>(
        pw, g2, be2, me2, v2, x, out, C_, 1);
}